// round 4
// baseline (speedup 1.0000x reference)
#include <cuda_runtime.h>

#define EPS     1e-5f
#define THREADS 64
#define NPTS    (64 * 1024)
#define NBLK    (NPTS / THREADS)

// Constant bank: folded W2 at float offset 0 (64x64), folded W3 at 4096 (64x64). 32KB.
__constant__ __align__(16) float cw[8192];
__device__   __align__(16) float fold_buf[8192];

typedef unsigned long long ull;

__device__ __forceinline__ ull fma2(ull a, ull b, ull c) {
    ull d; asm("fma.rn.f32x2 %0,%1,%2,%3;" : "=l"(d) : "l"(a), "l"(b), "l"(c)); return d;
}
__device__ __forceinline__ ull add2(ull a, ull b) {
    ull d; asm("add.rn.f32x2 %0,%1,%2;" : "=l"(d) : "l"(a), "l"(b)); return d;
}
__device__ __forceinline__ ull mul2(ull a, ull b) {
    ull d; asm("mul.rn.f32x2 %0,%1,%2;" : "=l"(d) : "l"(a), "l"(b)); return d;
}
__device__ __forceinline__ float sum2(ull a) {
    float x, y; asm("mov.b64 {%0,%1}, %2;" : "=f"(x), "=f"(y) : "l"(a)); return x + y;
}
__device__ __forceinline__ void unpk(ull v, float& lo, float& hi) {
    asm("mov.b64 {%0,%1}, %2;" : "=f"(lo), "=f"(hi) : "l"(v));
}
__device__ __forceinline__ ull pk2(float lo, float hi) {
    ull v; asm("mov.b64 %0, {%1,%2};" : "=l"(v) : "f"(lo), "f"(hi)); return v;
}
__device__ __forceinline__ ull pkc(float c) {
    unsigned int u = __float_as_uint(c);
    return ((ull)u << 32) | (ull)u;
}
__device__ __forceinline__ float frcp(float x) {
    float r; asm("rcp.approx.f32 %0,%1;" : "=f"(r) : "f"(x)); return r;
}
__device__ __forceinline__ float fex2(float x) {
    float r; asm("ex2.approx.f32 %0,%1;" : "=f"(r) : "f"(x)); return r;
}
// 16B constant-bank load -> LDC.128 (two packed f32x2 pairs)
__device__ __forceinline__ void ldc128(ull caddr, ull& lo, ull& hi) {
    asm("ld.const.v2.b64 {%0,%1}, [%2];" : "=l"(lo), "=l"(hi) : "l"(caddr));
}

// Branch-free exact-class GELU on a packed fp32x2 pair (A&S 7.1.26, |err|<=1.5e-7 abs).
__device__ __forceinline__ ull gelu2(ull s) {
    const ull C_ISQ2 = pkc(0.70710678118654752f);
    ull a = mul2(s & 0x7FFFFFFF7FFFFFFFULL, C_ISQ2);         // z = |x|/sqrt2
    ull d = fma2(a, pkc(0.3275911f), pkc(1.0f));
    float dl, dh; unpk(d, dl, dh);
    ull u = pk2(frcp(dl), frcp(dh));
    ull p = fma2(u, pkc(1.061405429f), pkc(-1.453152027f));
    p = fma2(u, p, pkc(1.421413741f));
    p = fma2(u, p, pkc(-0.284496736f));
    p = fma2(u, p, pkc(0.254829592f));
    p = mul2(p, u);
    ull m = mul2(mul2(a, a), pkc(-1.4426950408889634f));     // -z^2*log2e
    float ml, mh; unpk(m, ml, mh);
    ull e = pk2(fex2(ml), fex2(mh));
    ull pe = mul2(p, e);
    ull hm = mul2(a, C_ISQ2);                                // 0.5|x|
    ull r = fma2(pe ^ 0x8000000080000000ULL, hm, hm);        // 0.5|x|(1-PE)
    return fma2(s, pkc(0.5f), r);                            // + 0.5x
}

// ---- Fold BN into W2/W3, write to device buffer (copied to __constant__ afterwards) ----
__global__ void fold_kernel(const float* __restrict__ W2, const float* __restrict__ g2,
                            const float* __restrict__ v2,
                            const float* __restrict__ W3, const float* __restrict__ g3,
                            const float* __restrict__ v3)
{
    int i = blockIdx.x * blockDim.x + threadIdx.x;
    if (i < 4096) {
        int o = i >> 6;
        fold_buf[i]        = W2[i] * (g2[o] * rsqrtf(v2[o] + EPS));
        fold_buf[4096 + i] = W3[i] * (g3[o] * rsqrtf(v3[o] + EPS));
    }
}

__global__ void __launch_bounds__(THREADS, 4) edgeconv_mlp_kernel(
    const float* __restrict__ x,
    const float* __restrict__ W1, const float* __restrict__ g1, const float* __restrict__ b1,
    const float* __restrict__ m1, const float* __restrict__ v1,
    const float* __restrict__ g2, const float* __restrict__ b2, const float* __restrict__ m2,
    const float* __restrict__ v2,
    const float* __restrict__ g3, const float* __restrict__ b3, const float* __restrict__ m3,
    const float* __restrict__ v3,
    float* __restrict__ out)
{
    __shared__ float sw1[2048];   // folded W1 (64x32)
    __shared__ float sb[192];     // folded biases b1|b2|b3
    const int t = threadIdx.x;

    for (int i = t; i < 2048; i += THREADS) {
        int o = i >> 5;
        sw1[i] = W1[i] * (g1[o] * rsqrtf(v1[o] + EPS));
    }
    // THREADS == 64: each thread folds one bias per stage
    sb[t]       = b1[t] - m1[t] * (g1[t] * rsqrtf(v1[t] + EPS));
    sb[64 + t]  = b2[t] - m2[t] * (g2[t] * rsqrtf(v2[t] + EPS));
    sb[128 + t] = b3[t] - m3[t] * (g3[t] * rsqrtf(v3[t] + EPS));
    __syncthreads();

    const int p = blockIdx.x * THREADS + t;

    // constant-space base address of cw
    ull cb;
    asm("cvta.to.const.u64 %0, %1;" : "=l"(cb) : "l"((const void*)cw));

    // x[p, 0:32] as 16 packed pairs
    ull xp[16];
    {
        const ulonglong2* xg = (const ulonglong2*)(x + (size_t)p * 32);
        #pragma unroll
        for (int i = 0; i < 8; ++i) { ulonglong2 v = xg[i]; xp[2 * i] = v.x; xp[2 * i + 1] = v.y; }
    }

    // ---- Stage 1: 32 -> 64  (weights from SMEM crossbar) ----
    ull hp[32];
    #pragma unroll 2
    for (int o = 0; o < 64; o += 2) {
        const ulonglong2* w0 = (const ulonglong2*)(sw1 + o * 32);   // row o; row o+1 = +8 ull2
        ull a0 = 0, b0 = 0, a1 = 0, b1v = 0;
        #pragma unroll
        for (int q = 0; q < 8; ++q) {
            ulonglong2 wv0 = w0[q];
            ulonglong2 wv1 = w0[q + 8];
            a0  = fma2(wv0.x, xp[2 * q],     a0);
            b0  = fma2(wv0.y, xp[2 * q + 1], b0);
            a1  = fma2(wv1.x, xp[2 * q],     a1);
            b1v = fma2(wv1.y, xp[2 * q + 1], b1v);
        }
        float r0 = sum2(add2(a0, b0))  + sb[o];
        float r1 = sum2(add2(a1, b1v)) + sb[o + 1];
        hp[o >> 1] = gelu2(pk2(r0, r1));
    }

    // ---- Stage 2: 64 -> 64  (weights from constant port) ----
    ull hq[32];
    #pragma unroll 2
    for (int o = 0; o < 64; o += 2) {
        ull base = cb + (ull)(o * 256);          // row o = 256B; row o+1 = +256B
        ull a0 = 0, b0 = 0, a1 = 0, b1v = 0;
        #pragma unroll
        for (int c = 0; c < 16; ++c) {
            ull w0lo, w0hi, w1lo, w1hi;
            ldc128(base + c * 16,       w0lo, w0hi);
            ldc128(base + 256 + c * 16, w1lo, w1hi);
            a0  = fma2(w0lo, hp[2 * c],     a0);
            b0  = fma2(w0hi, hp[2 * c + 1], b0);
            a1  = fma2(w1lo, hp[2 * c],     a1);
            b1v = fma2(w1hi, hp[2 * c + 1], b1v);
        }
        float r0 = sum2(add2(a0, b0))  + sb[64 + o];
        float r1 = sum2(add2(a1, b1v)) + sb[64 + o + 1];
        hq[o >> 1] = gelu2(pk2(r0, r1));
    }

    // ---- Stage 3: 64 -> 64 (constant port), transposed store out[b, o, n] ----
    float* outp = out + (size_t)(p >> 10) * 65536 + (p & 1023);
    #pragma unroll 2
    for (int o = 0; o < 64; o += 2) {
        ull base = cb + (ull)(16384 + o * 256);
        ull a0 = 0, b0 = 0, a1 = 0, b1v = 0;
        #pragma unroll
        for (int c = 0; c < 16; ++c) {
            ull w0lo, w0hi, w1lo, w1hi;
            ldc128(base + c * 16,       w0lo, w0hi);
            ldc128(base + 256 + c * 16, w1lo, w1hi);
            a0  = fma2(w0lo, hq[2 * c],     a0);
            b0  = fma2(w0hi, hq[2 * c + 1], b0);
            a1  = fma2(w1lo, hq[2 * c],     a1);
            b1v = fma2(w1hi, hq[2 * c + 1], b1v);
        }
        float r0 = sum2(add2(a0, b0))  + sb[128 + o];
        float r1 = sum2(add2(a1, b1v)) + sb[128 + o + 1];
        ull g = gelu2(pk2(r0, r1));
        float glo, ghi; unpk(g, glo, ghi);
        outp[(size_t)o * 1024]       = glo;
        outp[(size_t)(o + 1) * 1024] = ghi;
    }
}

extern "C" void kernel_launch(void* const* d_in, const int* in_sizes, int n_in,
                              void* d_out, int out_size)
{
    const float* x  = (const float*)d_in[0];
    const float* W1 = (const float*)d_in[1];
    const float* g1 = (const float*)d_in[2];
    const float* b1 = (const float*)d_in[3];
    const float* m1 = (const float*)d_in[4];
    const float* v1 = (const float*)d_in[5];
    const float* W2 = (const float*)d_in[6];
    const float* g2 = (const float*)d_in[7];
    const float* b2 = (const float*)d_in[8];
    const float* m2 = (const float*)d_in[9];
    const float* v2 = (const float*)d_in[10];
    const float* W3 = (const float*)d_in[11];
    const float* g3 = (const float*)d_in[12];
    const float* b3 = (const float*)d_in[13];
    const float* m3 = (const float*)d_in[14];
    const float* v3 = (const float*)d_in[15];
    float* out = (float*)d_out;

    // 1) fold W2/W3 (+BN scale) into device buffer
    fold_kernel<<<16, 256>>>(W2, g2, v2, W3, g3, v3);

    // 2) device-to-device copy into the constant bank (graph-capturable memcpy node)
    void* src = nullptr;
    cudaGetSymbolAddress(&src, fold_buf);
    cudaMemcpyToSymbolAsync(cw, src, 8192 * sizeof(float), 0, cudaMemcpyDeviceToDevice, 0);

    // 3) main MLP kernel
    edgeconv_mlp_kernel<<<NBLK, THREADS>>>(
        x, W1, g1, b1, m1, v1, g2, b2, m2, v2, g3, b3, m3, v3, out);
}

// round 6
// speedup vs baseline: 1.5519x; 1.5519x over previous
#include <cuda_runtime.h>
#include <cuda_bf16.h>

#define EPS     1e-5f
#define THREADS 128
#define TILE_M  128
#define NPTS    (64 * 1024)
#define NBLK    (NPTS / TILE_M)   // 512 CTAs

// ---- SMEM byte layout ----
#define OFF_BIAS 0                       // 3*64 f32
#define OFF_W1H  1024                    // 64x32 bf16 frag-layout
#define OFF_W1L  (OFF_W1H + 4096)
#define OFF_W2H  (OFF_W1L + 4096)        // 64x64 bf16
#define OFF_W2L  (OFF_W2H + 8192)
#define OFF_W3H  (OFF_W2L + 8192)
#define OFF_W3L  (OFF_W3H + 8192)
#define OFF_BUF  (OFF_W3L + 8192)        // 41984: x staging (128x36 f32) / out transpose (64x132 f32)
#define BUF_STRIDE 132
#define X_STRIDE   36
#define SMEM_BYTES (OFF_BUF + 64 * BUF_STRIDE * 4)   // 75776 B -> 2 CTAs/SM

typedef unsigned long long ull;

// ---- packed fp32x2 helpers ----
__device__ __forceinline__ ull fma2(ull a, ull b, ull c) {
    ull d; asm("fma.rn.f32x2 %0,%1,%2,%3;" : "=l"(d) : "l"(a), "l"(b), "l"(c)); return d;
}
__device__ __forceinline__ ull add2(ull a, ull b) {
    ull d; asm("add.rn.f32x2 %0,%1,%2;" : "=l"(d) : "l"(a), "l"(b)); return d;
}
__device__ __forceinline__ ull mul2(ull a, ull b) {
    ull d; asm("mul.rn.f32x2 %0,%1,%2;" : "=l"(d) : "l"(a), "l"(b)); return d;
}
__device__ __forceinline__ void unpk(ull v, float& lo, float& hi) {
    asm("mov.b64 {%0,%1}, %2;" : "=f"(lo), "=f"(hi) : "l"(v));
}
__device__ __forceinline__ ull pk2(float lo, float hi) {
    ull v; asm("mov.b64 %0, {%1,%2};" : "=l"(v) : "f"(lo), "f"(hi)); return v;
}
__device__ __forceinline__ ull pkc(float c) {
    unsigned u = __float_as_uint(c); return ((ull)u << 32) | (ull)u;
}
__device__ __forceinline__ float frcp(float x) {
    float r; asm("rcp.approx.f32 %0,%1;" : "=f"(r) : "f"(x)); return r;
}
__device__ __forceinline__ float fex2(float x) {
    float r; asm("ex2.approx.f32 %0,%1;" : "=f"(r) : "f"(x)); return r;
}

// Branch-free exact-class GELU on a packed fp32x2 pair (A&S 7.1.26, |err|<=1.5e-7 abs).
__device__ __forceinline__ ull gelu2(ull s) {
    const ull C_ISQ2 = pkc(0.70710678118654752f);
    ull a = mul2(s & 0x7FFFFFFF7FFFFFFFULL, C_ISQ2);
    ull d = fma2(a, pkc(0.3275911f), pkc(1.0f));
    float dl, dh; unpk(d, dl, dh);
    ull u = pk2(frcp(dl), frcp(dh));
    ull p = fma2(u, pkc(1.061405429f), pkc(-1.453152027f));
    p = fma2(u, p, pkc(1.421413741f));
    p = fma2(u, p, pkc(-0.284496736f));
    p = fma2(u, p, pkc(0.254829592f));
    p = mul2(p, u);
    ull m = mul2(mul2(a, a), pkc(-1.4426950408889634f));
    float ml, mh; unpk(m, ml, mh);
    ull e = pk2(fex2(ml), fex2(mh));
    ull pe = mul2(p, e);
    ull hm = mul2(a, C_ISQ2);
    ull r = fma2(pe ^ 0x8000000080000000ULL, hm, hm);
    return fma2(s, pkc(0.5f), r);
}

// packed f32 pair -> (bf16x2 hi, bf16x2 lo-residual)
__device__ __forceinline__ void splitpair(ull v, unsigned& hb, unsigned& lb) {
    float f0, f1; unpk(v, f0, f1);
    unsigned h;
    asm("cvt.rn.bf16x2.f32 %0, %1, %2;" : "=r"(h) : "f"(f1), "f"(f0));  // lo half = f0
    float a0 = __uint_as_float(h << 16);
    float a1 = __uint_as_float(h & 0xFFFF0000u);
    float r0 = f0 - a0, r1 = f1 - a1;
    unsigned l;
    asm("cvt.rn.bf16x2.f32 %0, %1, %2;" : "=r"(l) : "f"(r1), "f"(r0));
    hb = h; lb = l;
}

// D += A(m16k16 bf16, row) @ B(k16n8 bf16, col); fp32 accum. Baseline PTX (sm_80+).
__device__ __forceinline__ void mma16816(float d[4], const unsigned a[4],
                                         unsigned b0, unsigned b1) {
    asm volatile(
        "mma.sync.aligned.m16n8k16.row.col.f32.bf16.bf16.f32 "
        "{%0,%1,%2,%3},{%4,%5,%6,%7},{%8,%9},{%0,%1,%2,%3};"
        : "+f"(d[0]), "+f"(d[1]), "+f"(d[2]), "+f"(d[3])
        : "r"(a[0]), "r"(a[1]), "r"(a[2]), "r"(a[3]), "r"(b0), "r"(b1));
}

// Weight store in B-fragment-friendly layout.
// 8B unit(o,t,p) holds bf16 {k=16t+2p, +1, +8, +9} for output o; t XOR-swizzled for
// conflict-free LDS.64 (bank-pair = 4*(t^o_low) + p spans the 16-lane phase).
template<int KT>
__device__ __forceinline__ void wstore(char* hib, char* lob, int o, int k, float w) {
    int t = k >> 4, kk = k & 15, pp = (kk & 7) >> 1, half = kk >> 3;
    int ts = t ^ (o & (KT - 1));
    int off = ((o * KT + ts) * 4 + pp) * 8 + half * 4 + (k & 1) * 2;
    __nv_bfloat16 hi = __float2bfloat16(w);
    float r = w - __bfloat162float(hi);
    *(__nv_bfloat16*)(hib + off) = hi;
    *(__nv_bfloat16*)(lob + off) = __float2bfloat16(r);
}

// One GEMM stage: D[2][8][4] = (Ah+Al) @ (Wh+Wl)^T, dropping lo*lo.
template<int KT>
__device__ __forceinline__ void run_stage(const char* whi, const char* wlo,
                                          unsigned Ah[2][4][4], unsigned Al[2][4][4],
                                          float D[2][8][4], int g, int p) {
    #pragma unroll
    for (int m = 0; m < 2; ++m)
        #pragma unroll
        for (int j = 0; j < 8; ++j)
            #pragma unroll
            for (int r = 0; r < 4; ++r) D[m][j][r] = 0.f;

    #pragma unroll
    for (int j = 0; j < 8; ++j) {
        int o = 8 * j + g;
        #pragma unroll
        for (int t = 0; t < KT; ++t) {
            int ts = t ^ (o & (KT - 1));
            int unit = (o * KT + ts) * 4 + p;
            ull wh = *(const ull*)(whi + unit * 8);
            ull wl = *(const ull*)(wlo + unit * 8);
            unsigned bh0 = (unsigned)wh, bh1 = (unsigned)(wh >> 32);
            unsigned bl0 = (unsigned)wl, bl1 = (unsigned)(wl >> 32);
            #pragma unroll
            for (int m = 0; m < 2; ++m) {
                mma16816(D[m][j], Ah[m][t], bh0, bh1);   // hi*hi
                mma16816(D[m][j], Ah[m][t], bl0, bl1);   // hi*lo
                mma16816(D[m][j], Al[m][t], bh0, bh1);   // lo*hi
            }
        }
    }
}

// bias + gelu + re-split into next stage's A fragments (pure per-thread; D layout == A layout)
__device__ __forceinline__ void epilogue_mid(float D[2][8][4], const float* bias,
                                             unsigned Ah[2][4][4], unsigned Al[2][4][4],
                                             int p) {
    #pragma unroll
    for (int j = 0; j < 8; ++j) {
        ull bp = *(const ull*)(bias + 8 * j + 2 * p);
        int t = j >> 1;
        int rb = (j & 1) ? 2 : 0;     // n-tile 2t -> A regs 0,1; 2t+1 -> regs 2,3
        #pragma unroll
        for (int m = 0; m < 2; ++m) {
            ull v0 = gelu2(add2(pk2(D[m][j][0], D[m][j][1]), bp));  // rows g
            ull v1 = gelu2(add2(pk2(D[m][j][2], D[m][j][3]), bp));  // rows g+8
            splitpair(v0, Ah[m][t][rb],     Al[m][t][rb]);
            splitpair(v1, Ah[m][t][rb + 1], Al[m][t][rb + 1]);
        }
    }
}

__global__ void __launch_bounds__(THREADS, 2) mlp_mma_kernel(
    const float* __restrict__ x,
    const float* __restrict__ W1, const float* __restrict__ g1, const float* __restrict__ b1,
    const float* __restrict__ m1, const float* __restrict__ v1,
    const float* __restrict__ W2, const float* __restrict__ g2, const float* __restrict__ b2,
    const float* __restrict__ m2, const float* __restrict__ v2,
    const float* __restrict__ W3, const float* __restrict__ g3, const float* __restrict__ b3,
    const float* __restrict__ m3, const float* __restrict__ v3,
    float* __restrict__ out)
{
    extern __shared__ char smem[];
    float* sbias = (float*)(smem + OFF_BIAS);
    const int tid = threadIdx.x;

    // ---- prologue: fold BN, split weights to bf16 hi/lo fragment layout ----
    if (tid < 64) {
        sbias[tid]       = b1[tid] - m1[tid] * (g1[tid] * rsqrtf(v1[tid] + EPS));
        sbias[64 + tid]  = b2[tid] - m2[tid] * (g2[tid] * rsqrtf(v2[tid] + EPS));
        sbias[128 + tid] = b3[tid] - m3[tid] * (g3[tid] * rsqrtf(v3[tid] + EPS));
    }
    for (int i = tid; i < 64 * 32; i += THREADS) {
        int o = i >> 5, k = i & 31;
        wstore<2>(smem + OFF_W1H, smem + OFF_W1L, o, k, W1[i] * (g1[o] * rsqrtf(v1[o] + EPS)));
    }
    for (int i = tid; i < 64 * 64; i += THREADS) {
        int o = i >> 6, k = i & 63;
        wstore<4>(smem + OFF_W2H, smem + OFF_W2L, o, k, W2[i] * (g2[o] * rsqrtf(v2[o] + EPS)));
        wstore<4>(smem + OFF_W3H, smem + OFF_W3L, o, k, W3[i] * (g3[o] * rsqrtf(v3[o] + EPS)));
    }

    // ---- stage x tile into SMEM (coalesced), padded stride ----
    float* sx = (float*)(smem + OFF_BUF);
    const size_t xbase = (size_t)blockIdx.x * TILE_M * 32;
    for (int i = tid; i < TILE_M * 32; i += THREADS) {
        int r = i >> 5, k = i & 31;
        sx[r * X_STRIDE + k] = x[xbase + i];
    }
    __syncthreads();

    const int lane = tid & 31, wid = tid >> 5;
    const int g = lane >> 2, p = lane & 3;

    // ---- build stage-1 A fragments from x (K=32: t=0,1) ----
    unsigned Ah[2][4][4], Al[2][4][4];
    #pragma unroll
    for (int m = 0; m < 2; ++m) {
        #pragma unroll
        for (int t = 0; t < 2; ++t) {
            int r0 = wid * 32 + m * 16 + g;
            int c0 = p * 2 + t * 16;
            splitpair(*(const ull*)(sx + r0 * X_STRIDE + c0),           Ah[m][t][0], Al[m][t][0]);
            splitpair(*(const ull*)(sx + (r0 + 8) * X_STRIDE + c0),     Ah[m][t][1], Al[m][t][1]);
            splitpair(*(const ull*)(sx + r0 * X_STRIDE + c0 + 8),       Ah[m][t][2], Al[m][t][2]);
            splitpair(*(const ull*)(sx + (r0 + 8) * X_STRIDE + c0 + 8), Ah[m][t][3], Al[m][t][3]);
        }
    }
    __syncthreads();   // all x reads done before OFF_BUF is reused as transpose buffer

    float D[2][8][4];

    run_stage<2>(smem + OFF_W1H, smem + OFF_W1L, Ah, Al, D, g, p);
    epilogue_mid(D, sbias, Ah, Al, p);

    run_stage<4>(smem + OFF_W2H, smem + OFF_W2L, Ah, Al, D, g, p);
    epilogue_mid(D, sbias + 64, Ah, Al, p);

    run_stage<4>(smem + OFF_W3H, smem + OFF_W3L, Ah, Al, D, g, p);

    // ---- final: bias + gelu -> SMEM transpose (conflict-free) -> coalesced STG ----
    float* buf = (float*)(smem + OFF_BUF);
    #pragma unroll
    for (int j = 0; j < 8; ++j) {
        ull bp = *(const ull*)(sbias + 128 + 8 * j + 2 * p);
        int o0 = 8 * j + 2 * p;
        #pragma unroll
        for (int m = 0; m < 2; ++m) {
            int r0 = wid * 32 + m * 16 + g;
            ull v0 = gelu2(add2(pk2(D[m][j][0], D[m][j][1]), bp));
            ull v1 = gelu2(add2(pk2(D[m][j][2], D[m][j][3]), bp));
            float f0, f1;
            unpk(v0, f0, f1);
            buf[o0 * BUF_STRIDE + r0]       = f0;
            buf[(o0 + 1) * BUF_STRIDE + r0] = f1;
            unpk(v1, f0, f1);
            buf[o0 * BUF_STRIDE + r0 + 8]       = f0;
            buf[(o0 + 1) * BUF_STRIDE + r0 + 8] = f1;
        }
    }
    __syncthreads();

    const int pbase = blockIdx.x * TILE_M;
    float* outp = out + (size_t)(pbase >> 10) * 65536 + (pbase & 1023);
    #pragma unroll 8
    for (int o = 0; o < 64; ++o)
        outp[(size_t)o * 1024 + tid] = buf[o * BUF_STRIDE + tid];
}

extern "C" void kernel_launch(void* const* d_in, const int* in_sizes, int n_in,
                              void* d_out, int out_size)
{
    const float* x  = (const float*)d_in[0];
    const float* W1 = (const float*)d_in[1];
    const float* g1 = (const float*)d_in[2];
    const float* b1 = (const float*)d_in[3];
    const float* m1 = (const float*)d_in[4];
    const float* v1 = (const float*)d_in[5];
    const float* W2 = (const float*)d_in[6];
    const float* g2 = (const float*)d_in[7];
    const float* b2 = (const float*)d_in[8];
    const float* m2 = (const float*)d_in[9];
    const float* v2 = (const float*)d_in[10];
    const float* W3 = (const float*)d_in[11];
    const float* g3 = (const float*)d_in[12];
    const float* b3 = (const float*)d_in[13];
    const float* m3 = (const float*)d_in[14];
    const float* v3 = (const float*)d_in[15];
    float* out = (float*)d_out;

    cudaFuncSetAttribute(mlp_mma_kernel,
                         cudaFuncAttributeMaxDynamicSharedMemorySize, SMEM_BYTES);

    mlp_mma_kernel<<<NBLK, THREADS, SMEM_BYTES>>>(
        x, W1, g1, b1, m1, v1, W2, g2, b2, m2, v2, W3, g3, b3, m3, v3, out);
}

// round 7
// speedup vs baseline: 1.9794x; 1.2755x over previous
#include <cuda_runtime.h>
#include <cuda_bf16.h>

#define EPS     1e-5f
#define THREADS 128
#define TILE_M  128
#define NPTS    (64 * 1024)
#define NBLK    (NPTS / TILE_M)   // 512 CTAs

// ---- pre-folded weights (bf16 hi/lo, fragment layout) + biases in device globals ----
// wbuf: W1H@0(4096) W1L@4096 W2H@8192(8192) W2L@16384 W3H@24576 W3L@32768 -> 40960 B
__device__ __align__(16) char  wbuf[40960];
__device__ __align__(16) float bbuf[192];

// ---- SMEM byte layout ----
#define OFF_BIAS 0                       // 192 f32 (pad to 1024)
#define OFF_W    1024                    // 40960 B weight block (same internal offsets as wbuf)
#define OFF_BUF  (OFF_W + 40960)         // x staging (128x36 f32) / out transpose (64x132 f32)
#define BUF_STRIDE 132
#define X_STRIDE   36
#define SMEM_BYTES (OFF_BUF + 64 * BUF_STRIDE * 4)   // 75776 B -> 2 CTAs/SM

typedef unsigned long long ull;

// ---- packed fp32x2 helpers ----
__device__ __forceinline__ ull fma2(ull a, ull b, ull c) {
    ull d; asm("fma.rn.f32x2 %0,%1,%2,%3;" : "=l"(d) : "l"(a), "l"(b), "l"(c)); return d;
}
__device__ __forceinline__ ull add2(ull a, ull b) {
    ull d; asm("add.rn.f32x2 %0,%1,%2;" : "=l"(d) : "l"(a), "l"(b)); return d;
}
__device__ __forceinline__ ull mul2(ull a, ull b) {
    ull d; asm("mul.rn.f32x2 %0,%1,%2;" : "=l"(d) : "l"(a), "l"(b)); return d;
}
__device__ __forceinline__ void unpk(ull v, float& lo, float& hi) {
    asm("mov.b64 {%0,%1}, %2;" : "=f"(lo), "=f"(hi) : "l"(v));
}
__device__ __forceinline__ ull pk2(float lo, float hi) {
    ull v; asm("mov.b64 %0, {%1,%2};" : "=l"(v) : "f"(lo), "f"(hi)); return v;
}
__device__ __forceinline__ ull pkc(float c) {
    unsigned u = __float_as_uint(c); return ((ull)u << 32) | (ull)u;
}
__device__ __forceinline__ float frcp(float x) {
    float r; asm("rcp.approx.f32 %0,%1;" : "=f"(r) : "f"(x)); return r;
}
__device__ __forceinline__ float fex2(float x) {
    float r; asm("ex2.approx.f32 %0,%1;" : "=f"(r) : "f"(x)); return r;
}

// Branch-free exact-class GELU on a packed fp32x2 pair (A&S 7.1.26, |err|<=1.5e-7 abs).
__device__ __forceinline__ ull gelu2(ull s) {
    const ull C_ISQ2 = pkc(0.70710678118654752f);
    ull a = mul2(s & 0x7FFFFFFF7FFFFFFFULL, C_ISQ2);
    ull d = fma2(a, pkc(0.3275911f), pkc(1.0f));
    float dl, dh; unpk(d, dl, dh);
    ull u = pk2(frcp(dl), frcp(dh));
    ull p = fma2(u, pkc(1.061405429f), pkc(-1.453152027f));
    p = fma2(u, p, pkc(1.421413741f));
    p = fma2(u, p, pkc(-0.284496736f));
    p = fma2(u, p, pkc(0.254829592f));
    p = mul2(p, u);
    ull m = mul2(mul2(a, a), pkc(-1.4426950408889634f));
    float ml, mh; unpk(m, ml, mh);
    ull e = pk2(fex2(ml), fex2(mh));
    ull pe = mul2(p, e);
    ull hm = mul2(a, C_ISQ2);
    ull r = fma2(pe ^ 0x8000000080000000ULL, hm, hm);
    return fma2(s, pkc(0.5f), r);
}

// packed f32 pair -> (bf16x2 hi, bf16x2 lo-residual)
__device__ __forceinline__ void splitpair(ull v, unsigned& hb, unsigned& lb) {
    float f0, f1; unpk(v, f0, f1);
    unsigned h;
    asm("cvt.rn.bf16x2.f32 %0, %1, %2;" : "=r"(h) : "f"(f1), "f"(f0));
    float a0 = __uint_as_float(h << 16);
    float a1 = __uint_as_float(h & 0xFFFF0000u);
    float r0 = f0 - a0, r1 = f1 - a1;
    unsigned l;
    asm("cvt.rn.bf16x2.f32 %0, %1, %2;" : "=r"(l) : "f"(r1), "f"(r0));
    hb = h; lb = l;
}

// D += A(m16k16 bf16, row) @ B(k16n8 bf16, col); fp32 accum. Baseline PTX (sm_80+).
__device__ __forceinline__ void mma16816(float d[4], const unsigned a[4],
                                         unsigned b0, unsigned b1) {
    asm volatile(
        "mma.sync.aligned.m16n8k16.row.col.f32.bf16.bf16.f32 "
        "{%0,%1,%2,%3},{%4,%5,%6,%7},{%8,%9},{%0,%1,%2,%3};"
        : "+f"(d[0]), "+f"(d[1]), "+f"(d[2]), "+f"(d[3])
        : "r"(a[0]), "r"(a[1]), "r"(a[2]), "r"(a[3]), "r"(b0), "r"(b1));
}

// Fragment-layout offset: 8B unit(o,t,p) holds bf16 {k=16t+2p,+1,+8,+9} for output o;
// t XOR-swizzled so the 16-lane LDS.64 phase is conflict-free.
template<int KT>
__device__ __forceinline__ int woff(int o, int k) {
    int t = k >> 4, kk = k & 15, pp = (kk & 7) >> 1, half = kk >> 3;
    int ts = t ^ (o & (KT - 1));
    return ((o * KT + ts) * 4 + pp) * 8 + half * 4 + (k & 1) * 2;
}

// ---- one-shot fold kernel: BN-fold + bf16 hi/lo split into fragment layout ----
__global__ void fold_kernel(
    const float* __restrict__ W1, const float* __restrict__ g1, const float* __restrict__ b1,
    const float* __restrict__ m1, const float* __restrict__ v1,
    const float* __restrict__ W2, const float* __restrict__ g2, const float* __restrict__ b2,
    const float* __restrict__ m2, const float* __restrict__ v2,
    const float* __restrict__ W3, const float* __restrict__ g3, const float* __restrict__ b3,
    const float* __restrict__ m3, const float* __restrict__ v3)
{
    int i = blockIdx.x * blockDim.x + threadIdx.x;
    if (i < 2048) {                               // W1 [64x32]
        int o = i >> 5, k = i & 31;
        float w = W1[i] * (g1[o] * rsqrtf(v1[o] + EPS));
        __nv_bfloat16 hi = __float2bfloat16(w);
        int off = woff<2>(o, k);
        *(__nv_bfloat16*)(wbuf + off)        = hi;
        *(__nv_bfloat16*)(wbuf + 4096 + off) = __float2bfloat16(w - __bfloat162float(hi));
    } else if (i < 2048 + 4096) {                 // W2 [64x64]
        int j = i - 2048, o = j >> 6, k = j & 63;
        float w = W2[j] * (g2[o] * rsqrtf(v2[o] + EPS));
        __nv_bfloat16 hi = __float2bfloat16(w);
        int off = woff<4>(o, k);
        *(__nv_bfloat16*)(wbuf + 8192 + off)  = hi;
        *(__nv_bfloat16*)(wbuf + 16384 + off) = __float2bfloat16(w - __bfloat162float(hi));
    } else if (i < 2048 + 8192) {                 // W3 [64x64]
        int j = i - 6144, o = j >> 6, k = j & 63;
        float w = W3[j] * (g3[o] * rsqrtf(v3[o] + EPS));
        __nv_bfloat16 hi = __float2bfloat16(w);
        int off = woff<4>(o, k);
        *(__nv_bfloat16*)(wbuf + 24576 + off) = hi;
        *(__nv_bfloat16*)(wbuf + 32768 + off) = __float2bfloat16(w - __bfloat162float(hi));
    }
    if (i < 64) {
        bbuf[i]       = b1[i] - m1[i] * (g1[i] * rsqrtf(v1[i] + EPS));
        bbuf[64 + i]  = b2[i] - m2[i] * (g2[i] * rsqrtf(v2[i] + EPS));
        bbuf[128 + i] = b3[i] - m3[i] * (g3[i] * rsqrtf(v3[i] + EPS));
    }
}

// One GEMM stage: D[2][8][4] = (Ah+Al) @ (Wh+Wl)^T, dropping lo*lo.
template<int KT>
__device__ __forceinline__ void run_stage(const char* whi, const char* wlo,
                                          unsigned Ah[2][4][4], unsigned Al[2][4][4],
                                          float D[2][8][4], int g, int p) {
    #pragma unroll
    for (int m = 0; m < 2; ++m)
        #pragma unroll
        for (int j = 0; j < 8; ++j)
            #pragma unroll
            for (int r = 0; r < 4; ++r) D[m][j][r] = 0.f;

    #pragma unroll
    for (int j = 0; j < 8; ++j) {
        int o = 8 * j + g;
        #pragma unroll
        for (int t = 0; t < KT; ++t) {
            int ts = t ^ (o & (KT - 1));
            int unit = (o * KT + ts) * 4 + p;
            ull wh = *(const ull*)(whi + unit * 8);
            ull wl = *(const ull*)(wlo + unit * 8);
            unsigned bh0 = (unsigned)wh, bh1 = (unsigned)(wh >> 32);
            unsigned bl0 = (unsigned)wl, bl1 = (unsigned)(wl >> 32);
            #pragma unroll
            for (int m = 0; m < 2; ++m) {
                mma16816(D[m][j], Ah[m][t], bh0, bh1);
                mma16816(D[m][j], Ah[m][t], bl0, bl1);
                mma16816(D[m][j], Al[m][t], bh0, bh1);
            }
        }
    }
}

// bias + gelu + re-split into next stage's A fragments (pure per-thread register work)
__device__ __forceinline__ void epilogue_mid(float D[2][8][4], const float* bias,
                                             unsigned Ah[2][4][4], unsigned Al[2][4][4],
                                             int p) {
    #pragma unroll
    for (int j = 0; j < 8; ++j) {
        ull bp = *(const ull*)(bias + 8 * j + 2 * p);
        int t = j >> 1;
        int rb = (j & 1) ? 2 : 0;
        #pragma unroll
        for (int m = 0; m < 2; ++m) {
            ull v0 = gelu2(add2(pk2(D[m][j][0], D[m][j][1]), bp));
            ull v1 = gelu2(add2(pk2(D[m][j][2], D[m][j][3]), bp));
            splitpair(v0, Ah[m][t][rb],     Al[m][t][rb]);
            splitpair(v1, Ah[m][t][rb + 1], Al[m][t][rb + 1]);
        }
    }
}

__global__ void __launch_bounds__(THREADS, 2) mlp_mma_kernel(
    const float* __restrict__ x, float* __restrict__ out)
{
    extern __shared__ char smem[];
    const int tid = threadIdx.x;

    // ---- prologue: flat copy of pre-folded weights + biases into SMEM ----
    {
        const uint4* src = (const uint4*)wbuf;
        uint4* dst = (uint4*)(smem + OFF_W);
        #pragma unroll
        for (int i = 0; i < 20; ++i) dst[tid + i * THREADS] = src[tid + i * THREADS];
        if (tid < 48) ((uint4*)(smem + OFF_BIAS))[tid] = ((const uint4*)bbuf)[tid];
    }

    // ---- stage x tile into SMEM (coalesced), padded stride ----
    float* sx = (float*)(smem + OFF_BUF);
    const size_t xbase = (size_t)blockIdx.x * TILE_M * 32;
    for (int i = tid; i < TILE_M * 32; i += THREADS) {
        int r = i >> 5, k = i & 31;
        sx[r * X_STRIDE + k] = x[xbase + i];
    }
    __syncthreads();

    const float* sbias = (const float*)(smem + OFF_BIAS);
    const int lane = tid & 31, wid = tid >> 5;
    const int g = lane >> 2, p = lane & 3;

    // ---- build stage-1 A fragments from x (K=32: t=0,1) ----
    unsigned Ah[2][4][4], Al[2][4][4];
    #pragma unroll
    for (int m = 0; m < 2; ++m) {
        #pragma unroll
        for (int t = 0; t < 2; ++t) {
            int r0 = wid * 32 + m * 16 + g;
            int c0 = p * 2 + t * 16;
            splitpair(*(const ull*)(sx + r0 * X_STRIDE + c0),           Ah[m][t][0], Al[m][t][0]);
            splitpair(*(const ull*)(sx + (r0 + 8) * X_STRIDE + c0),     Ah[m][t][1], Al[m][t][1]);
            splitpair(*(const ull*)(sx + r0 * X_STRIDE + c0 + 8),       Ah[m][t][2], Al[m][t][2]);
            splitpair(*(const ull*)(sx + (r0 + 8) * X_STRIDE + c0 + 8), Ah[m][t][3], Al[m][t][3]);
        }
    }
    __syncthreads();   // x reads done before OFF_BUF is reused as transpose buffer

    float D[2][8][4];

    run_stage<2>(smem + OFF_W,         smem + OFF_W + 4096,  Ah, Al, D, g, p);
    epilogue_mid(D, sbias, Ah, Al, p);

    run_stage<4>(smem + OFF_W + 8192,  smem + OFF_W + 16384, Ah, Al, D, g, p);
    epilogue_mid(D, sbias + 64, Ah, Al, p);

    run_stage<4>(smem + OFF_W + 24576, smem + OFF_W + 32768, Ah, Al, D, g, p);

    // ---- final: bias + gelu -> SMEM transpose (conflict-free) -> coalesced STG ----
    float* buf = (float*)(smem + OFF_BUF);
    #pragma unroll
    for (int j = 0; j < 8; ++j) {
        ull bp = *(const ull*)(sbias + 128 + 8 * j + 2 * p);
        int o0 = 8 * j + 2 * p;
        #pragma unroll
        for (int m = 0; m < 2; ++m) {
            int r0 = wid * 32 + m * 16 + g;
            ull v0 = gelu2(add2(pk2(D[m][j][0], D[m][j][1]), bp));
            ull v1 = gelu2(add2(pk2(D[m][j][2], D[m][j][3]), bp));
            float f0, f1;
            unpk(v0, f0, f1);
            buf[o0 * BUF_STRIDE + r0]       = f0;
            buf[(o0 + 1) * BUF_STRIDE + r0] = f1;
            unpk(v1, f0, f1);
            buf[o0 * BUF_STRIDE + r0 + 8]       = f0;
            buf[(o0 + 1) * BUF_STRIDE + r0 + 8] = f1;
        }
    }
    __syncthreads();

    const int pbase = blockIdx.x * TILE_M;
    float* outp = out + (size_t)(pbase >> 10) * 65536 + (pbase & 1023);
    #pragma unroll 8
    for (int o = 0; o < 64; ++o)
        outp[(size_t)o * 1024 + tid] = buf[o * BUF_STRIDE + tid];
}

extern "C" void kernel_launch(void* const* d_in, const int* in_sizes, int n_in,
                              void* d_out, int out_size)
{
    const float* x  = (const float*)d_in[0];
    const float* W1 = (const float*)d_in[1];
    const float* g1 = (const float*)d_in[2];
    const float* b1 = (const float*)d_in[3];
    const float* m1 = (const float*)d_in[4];
    const float* v1 = (const float*)d_in[5];
    const float* W2 = (const float*)d_in[6];
    const float* g2 = (const float*)d_in[7];
    const float* b2 = (const float*)d_in[8];
    const float* m2 = (const float*)d_in[9];
    const float* v2 = (const float*)d_in[10];
    const float* W3 = (const float*)d_in[11];
    const float* g3 = (const float*)d_in[12];
    const float* b3 = (const float*)d_in[13];
    const float* m3 = (const float*)d_in[14];
    const float* v3 = (const float*)d_in[15];
    float* out = (float*)d_out;

    fold_kernel<<<40, 256>>>(W1, g1, b1, m1, v1, W2, g2, b2, m2, v2, W3, g3, b3, m3, v3);

    cudaFuncSetAttribute(mlp_mma_kernel,
                         cudaFuncAttributeMaxDynamicSharedMemorySize, SMEM_BYTES);
    mlp_mma_kernel<<<NBLK, THREADS, SMEM_BYTES>>>(x, out);
}